// round 2
// baseline (speedup 1.0000x reference)
#include <cuda_runtime.h>
#include <cstdint>

// Problem constants
#define NVEH 16384
#define NT   256
#define HDIM 20

// 1 thread = 1 vehicle. 128 threads/block -> 128 blocks (1 per SM).
#define TPB  128
#define NBLK (NVEH / TPB)   // 128

// ---------- packed f32x2 helpers (sm_103a) ----------
__device__ __forceinline__ void ffma2(unsigned long long& d,
                                      unsigned long long a,
                                      unsigned long long b) {
    asm("fma.rn.f32x2 %0, %1, %2, %0;" : "+l"(d) : "l"(a), "l"(b));
}
__device__ __forceinline__ unsigned long long dup2(float x) {
    unsigned long long r;
    asm("mov.b64 %0, {%1, %1};" : "=l"(r) : "f"(x));
    return r;
}
__device__ __forceinline__ float lo32(unsigned long long v) {
    float f;
    asm("{ .reg .b32 hi; mov.b64 {%0, hi}, %1; }" : "=f"(f) : "l"(v));
    return f;
}
__device__ __forceinline__ float hi32(unsigned long long v) {
    float f;
    asm("{ .reg .b32 lo; mov.b64 {lo, %0}, %1; }" : "=f"(f) : "l"(v));
    return f;
}

// ---------- fast, overflow-safe activations ----------
// tanh(x) = sign(x) * (1 - e) / (1 + e),  e = exp(-2|x|)
__device__ __forceinline__ float fast_tanh(float x) {
    float a = fabsf(x);
    float e = __expf(-2.0f * a);
    float r = __fdividef(1.0f - e, 1.0f + e);
    return copysignf(r, x);
}
// sigmoid(x) = 0.5 * (1 + tanh(x/2))
__device__ __forceinline__ float fast_sig(float x) {
    float a = fabsf(x);
    float e = __expf(-a);
    float r = __fdividef(1.0f - e, 1.0f + e);
    return fmaf(0.5f, copysignf(r, x), 0.5f);
}

__global__ __launch_bounds__(TPB)
void rnncf_kernel(const float* __restrict__ lead_inputs,  // (NVEH, NT, 2)
                  const float* __restrict__ init_state,   // (NVEH, 2)
                  const float* __restrict__ h0,           // (NVEH, H)
                  const float* __restrict__ c0,           // (NVEH, H)
                  const float* __restrict__ W,            // (3, 80)
                  const float* __restrict__ U,            // (20, 80)
                  const float* __restrict__ b,            // (80,)
                  const float* __restrict__ Wd,           // (20, 1)
                  const float* __restrict__ bd,           // (1,)
                  float* __restrict__ out,
                  int out_size)
{
    // Packed weights, warp-uniform access. Row r (0..23), unit u (0..19):
    //   entry = { pair(W_i, W_f), pair(W_g, W_o) }  (16B, one LDS.128)
    // rows 0..2 = W, rows 3..22 = U, row 23 = bias.
    __shared__ ulonglong2 Wp[24 * HDIM];   // 7680 B

    {
        float* Wf = reinterpret_cast<float*>(Wp);
        for (int idx = threadIdx.x; idx < 24 * 80; idx += TPB) {
            int k = idx / 80, rem = idx % 80;
            int u = rem >> 2, g = rem & 3;
            float val;
            if (k < 3)       val = W[k * 80 + g * HDIM + u];
            else if (k < 23) val = U[(k - 3) * 80 + g * HDIM + u];
            else             val = b[g * HDIM + u];
            Wf[idx] = val;
        }
    }
    __syncthreads();

    const int v = blockIdx.x * TPB + threadIdx.x;

    // Per-thread (per-vehicle) state: full hidden + cell in registers.
    float hh[HDIM], cc[HDIM], wd[HDIM];
#pragma unroll
    for (int u = 0; u < HDIM; ++u) {
        hh[u] = h0[v * HDIM + u];
        cc[u] = c0[v * HDIM + u];
        wd[u] = Wd[u];
    }
    const float bdv = bd[0];
    float pos = init_state[2 * v];
    float spd = init_state[2 * v + 1];

    const float2* lead2 = reinterpret_cast<const float2*>(lead_inputs) + (size_t)v * NT;
    float2 cur = lead2[0];

    const bool write_extras = (out_size >= NT * NVEH + NVEH + 2 * NVEH * HDIM);

#pragma unroll 1
    for (int t = 0; t < NT; ++t) {
        // prefetch next step's lead data (hides gmem latency behind compute)
        const int tn = (t + 1 < NT) ? (t + 1) : (NT - 1);
        float2 nxt = lead2[tn];

        const float x0 = (cur.x - pos) * (1.0f / 100.0f);
        const float x1 = spd * (1.0f / 40.0f);
        const float x2 = cur.y * (1.0f / 40.0f);

        unsigned long long acc_if[HDIM], acc_go[HDIM];
        // init from bias row (row 23)
#pragma unroll
        for (int u = 0; u < HDIM; ++u) {
            ulonglong2 bb = Wp[23 * HDIM + u];
            acc_if[u] = bb.x;
            acc_go[u] = bb.y;
        }

        // one input row: 20 uniform LDS.128 + 40 FFMA2
#define ROW(r, m)                                              \
        {                                                      \
            unsigned long long md = dup2(m);                   \
            _Pragma("unroll")                                  \
            for (int u = 0; u < HDIM; ++u) {                   \
                ulonglong2 w = Wp[(r) * HDIM + u];             \
                ffma2(acc_if[u], w.x, md);                     \
                ffma2(acc_go[u], w.y, md);                     \
            }                                                  \
        }

        ROW(0, x0)
        ROW(1, x1)
        ROW(2, x2)
#pragma unroll
        for (int k = 0; k < HDIM; ++k) {
            ROW(3 + k, hh[k])
        }
#undef ROW

        // gates -> c,h update; h @ Wd
        float p = 0.0f;
#pragma unroll
        for (int u = 0; u < HDIM; ++u) {
            float zi = lo32(acc_if[u]);
            float zf = hi32(acc_if[u]);
            float zg = lo32(acc_go[u]);
            float zo = hi32(acc_go[u]);
            float ig = fast_sig(zi);
            float fg = fast_sig(zf);
            float gg = fast_tanh(zg);
            float og = fast_sig(zo);
            float cn = fmaf(fg, cc[u], ig * gg);
            cc[u] = cn;
            float hn = og * fast_tanh(cn);
            hh[u] = hn;
            p = fmaf(hn, wd[u], p);
        }

        const float o_scalar = p + bdv;
        const float a = fmaf(7.0f, o_scalar, -4.0f);   // (MAXA-MINA)*out + MINA
        spd = fmaf(0.1f, a, spd);
        pos = fmaf(0.1f, a, pos);

        out[(size_t)t * NVEH + v] = pos;   // fully coalesced across the warp

        cur = nxt;
    }

    if (write_extras) {
        out[(size_t)NT * NVEH + v] = spd;
        float* hout = out + (size_t)NT * NVEH + NVEH;
        float* cout = hout + (size_t)NVEH * HDIM;
#pragma unroll
        for (int u = 0; u < HDIM; ++u) {
            hout[v * HDIM + u] = hh[u];
            cout[v * HDIM + u] = cc[u];
        }
    }
}

extern "C" void kernel_launch(void* const* d_in, const int* in_sizes, int n_in,
                              void* d_out, int out_size) {
    const float* lead_inputs = (const float*)d_in[0];
    const float* init_state  = (const float*)d_in[1];
    const float* h0          = (const float*)d_in[2];
    const float* c0          = (const float*)d_in[3];
    const float* W           = (const float*)d_in[4];
    const float* U           = (const float*)d_in[5];
    const float* b           = (const float*)d_in[6];
    const float* Wd          = (const float*)d_in[7];
    const float* bd          = (const float*)d_in[8];

    rnncf_kernel<<<NBLK, TPB>>>(lead_inputs, init_state, h0, c0,
                                W, U, b, Wd, bd,
                                (float*)d_out, out_size);
}